// round 5
// baseline (speedup 1.0000x reference)
#include <cuda_runtime.h>
#include <cooperative_groups.h>

namespace cg = cooperative_groups;

#define HW 3136

// One cluster (4 CTAs x 256 thr) per sample b. CTA rank r owns channels
// [r*64, r*64+64). Pipeline: pool -> DSMEM gather -> kgen GEMM -> depthwise conv.
__global__ void __cluster_dims__(4, 1, 1) __launch_bounds__(256)
fused_kernel(const float* __restrict__ x, const float* __restrict__ Wk,
             const float* __restrict__ bk, float* __restrict__ out)
{
    __shared__ float pooled_seg[64];    // this CTA's 64 pooled channels (peer-readable)
    __shared__ float pooled_full[256];  // gathered full vector
    __shared__ float kern_seg[576];     // 64 planes x 9 taps

    cg::cluster_group cluster = cg::this_cluster();
    const int rank = (int)cluster.block_rank();
    const int b = blockIdx.x >> 2;
    const int tid = threadIdx.x;
    const int warp = tid >> 5, lane = tid & 31;
    const int c_base = rank * 64;
    const size_t sample_off = (size_t)b * 256 * HW;

    // ---------- phase 1: pool 64 planes (warp w pools planes w*8..w*8+7) ----------
    #pragma unroll
    for (int pp = 0; pp < 8; pp++) {
        const int lc = warp * 8 + pp;
        const float4* xp = reinterpret_cast<const float4*>(
            x + sample_off + (size_t)(c_base + lc) * HW);
        float s = 0.f;
        for (int i = lane; i < 784; i += 32) {
            float4 v = __ldg(xp + i);
            s += (v.x + v.y) + (v.z + v.w);
        }
        #pragma unroll
        for (int o = 16; o; o >>= 1) s += __shfl_xor_sync(0xffffffffu, s, o);
        if (lane == 0) pooled_seg[lc] = s * (1.0f / 3136.f);
    }
    cluster.sync();   // all 4 CTAs' pooled_seg visible

    // ---------- phase 2: gather full pooled vector via DSMEM ----------
    {
        float* peer = cluster.map_shared_rank(pooled_seg, tid >> 6);
        pooled_full[tid] = peer[tid & 63];
    }
    cluster.sync();   // close peer-smem window before anyone races ahead

    // ---------- phase 3: kern = relu(pooled @ Wk^T + bk), rows [c_base*9, +576) ----------
    // 8 warps x 9 groups of 8 rows; 64 batched L2 loads per group for MLP.
    const int o_base = c_base * 9;
    for (int g = 0; g < 9; g++) {
        const int lo0 = warp * 72 + g * 8;
        const float* wp0 = Wk + (size_t)(o_base + lo0) * 256 + lane;
        float a0 = 0.f, a1 = 0.f, a2 = 0.f, a3 = 0.f;
        float a4 = 0.f, a5 = 0.f, a6 = 0.f, a7 = 0.f;
        #pragma unroll
        for (int i = 0; i < 8; i++) {
            const float p = pooled_full[lane + 32 * i];
            const float* wp = wp0 + 32 * i;
            a0 = fmaf(__ldg(wp + 0 * 256), p, a0);
            a1 = fmaf(__ldg(wp + 1 * 256), p, a1);
            a2 = fmaf(__ldg(wp + 2 * 256), p, a2);
            a3 = fmaf(__ldg(wp + 3 * 256), p, a3);
            a4 = fmaf(__ldg(wp + 4 * 256), p, a4);
            a5 = fmaf(__ldg(wp + 5 * 256), p, a5);
            a6 = fmaf(__ldg(wp + 6 * 256), p, a6);
            a7 = fmaf(__ldg(wp + 7 * 256), p, a7);
        }
        #pragma unroll
        for (int o = 16; o; o >>= 1) {
            a0 += __shfl_xor_sync(0xffffffffu, a0, o);
            a1 += __shfl_xor_sync(0xffffffffu, a1, o);
            a2 += __shfl_xor_sync(0xffffffffu, a2, o);
            a3 += __shfl_xor_sync(0xffffffffu, a3, o);
            a4 += __shfl_xor_sync(0xffffffffu, a4, o);
            a5 += __shfl_xor_sync(0xffffffffu, a5, o);
            a6 += __shfl_xor_sync(0xffffffffu, a6, o);
            a7 += __shfl_xor_sync(0xffffffffu, a7, o);
        }
        if (lane == 0) {
            const float* bp = bk + o_base + lo0;
            kern_seg[lo0 + 0] = fmaxf(a0 + __ldg(bp + 0), 0.f);
            kern_seg[lo0 + 1] = fmaxf(a1 + __ldg(bp + 1), 0.f);
            kern_seg[lo0 + 2] = fmaxf(a2 + __ldg(bp + 2), 0.f);
            kern_seg[lo0 + 3] = fmaxf(a3 + __ldg(bp + 3), 0.f);
            kern_seg[lo0 + 4] = fmaxf(a4 + __ldg(bp + 4), 0.f);
            kern_seg[lo0 + 5] = fmaxf(a5 + __ldg(bp + 5), 0.f);
            kern_seg[lo0 + 6] = fmaxf(a6 + __ldg(bp + 6), 0.f);
            kern_seg[lo0 + 7] = fmaxf(a7 + __ldg(bp + 7), 0.f);
        }
    }
    __syncthreads();

    // ---------- phase 4: depthwise 3x3 on our 64 planes (x is L2-hot) ----------
    if (tid >= 224) return;                 // no barriers below
    const int pl_half = tid / 112;          // which of the 2 planes per iteration
    const int u  = tid % 112;
    const int cgp = u % 14;
    const int rg  = u / 14;
    const int xc = cgp * 4;
    const int y0 = rg * 7;
    const bool lok = cgp > 0;
    const bool rok = cgp < 13;

    for (int it = 0; it < 32; it++) {
        const int lc = it * 2 + pl_half;
        const size_t plane = (size_t)b * 256 + c_base + lc;
        const float* kp = kern_seg + lc * 9;
        const float k0 = kp[0], k1 = kp[1], k2 = kp[2];
        const float k3 = kp[3], k4 = kp[4], k5 = kp[5];
        const float k6 = kp[6], k7 = kp[7], k8 = kp[8];

        const float* xp = x + plane * HW + xc;

        float4 ca; float la, ra;
        float4 cb; float lb, rb;

        if (rg > 0) {
            const float* p = xp + (y0 - 1) * 56;
            ca = __ldg(reinterpret_cast<const float4*>(p));
            la = lok ? __ldg(p - 1) : 0.f;
            ra = rok ? __ldg(p + 4) : 0.f;
        } else {
            ca = make_float4(0.f, 0.f, 0.f, 0.f); la = 0.f; ra = 0.f;
        }
        {
            const float* p = xp + y0 * 56;
            cb = __ldg(reinterpret_cast<const float4*>(p));
            lb = lok ? __ldg(p - 1) : 0.f;
            rb = rok ? __ldg(p + 4) : 0.f;
        }

        float* op = out + plane * HW + y0 * 56 + xc;

        #pragma unroll
        for (int r = 0; r < 7; r++) {
            const int y = y0 + r + 1;
            float4 cc; float lc2, rc;
            if (y < 56) {
                const float* p = xp + y * 56;
                cc = __ldg(reinterpret_cast<const float4*>(p));
                lc2 = lok ? __ldg(p - 1) : 0.f;
                rc  = rok ? __ldg(p + 4) : 0.f;
            } else {
                cc = make_float4(0.f, 0.f, 0.f, 0.f); lc2 = 0.f; rc = 0.f;
            }

            float4 acc;
            acc.x = k0 * la;
            acc.x = fmaf(k1, ca.x, acc.x); acc.x = fmaf(k2, ca.y, acc.x);
            acc.x = fmaf(k3, lb,   acc.x); acc.x = fmaf(k4, cb.x, acc.x);
            acc.x = fmaf(k5, cb.y, acc.x); acc.x = fmaf(k6, lc2,  acc.x);
            acc.x = fmaf(k7, cc.x, acc.x); acc.x = fmaf(k8, cc.y, acc.x);

            acc.y = k0 * ca.x;
            acc.y = fmaf(k1, ca.y, acc.y); acc.y = fmaf(k2, ca.z, acc.y);
            acc.y = fmaf(k3, cb.x, acc.y); acc.y = fmaf(k4, cb.y, acc.y);
            acc.y = fmaf(k5, cb.z, acc.y); acc.y = fmaf(k6, cc.x, acc.y);
            acc.y = fmaf(k7, cc.y, acc.y); acc.y = fmaf(k8, cc.z, acc.y);

            acc.z = k0 * ca.y;
            acc.z = fmaf(k1, ca.z, acc.z); acc.z = fmaf(k2, ca.w, acc.z);
            acc.z = fmaf(k3, cb.y, acc.z); acc.z = fmaf(k4, cb.z, acc.z);
            acc.z = fmaf(k5, cb.w, acc.z); acc.z = fmaf(k6, cc.y, acc.z);
            acc.z = fmaf(k7, cc.z, acc.z); acc.z = fmaf(k8, cc.w, acc.z);

            acc.w = k0 * ca.z;
            acc.w = fmaf(k1, ca.w, acc.w); acc.w = fmaf(k2, ra,   acc.w);
            acc.w = fmaf(k3, cb.z, acc.w); acc.w = fmaf(k4, cb.w, acc.w);
            acc.w = fmaf(k5, rb,   acc.w); acc.w = fmaf(k6, cc.z, acc.w);
            acc.w = fmaf(k7, cc.w, acc.w); acc.w = fmaf(k8, rc,   acc.w);

            __stcs(reinterpret_cast<float4*>(op + r * 56), acc);

            ca = cb; la = lb; ra = rb;
            cb = cc; lb = lc2; rb = rc;
        }
    }
}

extern "C" void kernel_launch(void* const* d_in, const int* in_sizes, int n_in,
                              void* d_out, int out_size) {
    const float* x  = (const float*)d_in[0];   // [32,256,56,56]
    const float* Wk = (const float*)d_in[1];   // [2304,256]
    const float* bk = (const float*)d_in[2];   // [2304]
    float* out = (float*)d_out;

    fused_kernel<<<128, 256>>>(x, Wk, bk, out);
}

// round 6
// speedup vs baseline: 2.7066x; 2.7066x over previous
#include <cuda_runtime.h>

#define HW 3136

__device__ float    g_pooled[32 * 256];
__device__ unsigned g_done[32];

__global__ void reset_kernel() {
    if (threadIdx.x < 32) g_done[threadIdx.x] = 0u;
}

// grid = 4096 blocks x 256 threads. Block (b, pair) owns planes b*256 + pair*2 + {0,1}.
// pool own 2 planes -> publish -> spin for sample b complete -> own 18 kern rows -> conv.
__global__ void __launch_bounds__(256) fused_kernel(const float* __restrict__ x,
                                                    const float* __restrict__ Wk,
                                                    const float* __restrict__ bk,
                                                    float* __restrict__ out)
{
    __shared__ float part[8];       // 4 warp partials x 2 planes
    __shared__ float psh[256];      // pooled vector of sample b
    __shared__ float kern_s[18];    // 2 planes x 9 taps

    const int bid  = blockIdx.x;
    const int b    = bid >> 7;          // sample
    const int pair = bid & 127;
    const int tid  = threadIdx.x;
    const int warp = tid >> 5, lane = tid & 31;
    const int c0   = pair * 2;          // first local channel

    // ---------- phase 1: pool our two planes ----------
    {
        const int sub = tid >> 7;       // 0/1 -> plane c0+sub
        const int st  = tid & 127;
        const float4* xp = reinterpret_cast<const float4*>(
            x + ((size_t)b * 256 + c0 + sub) * HW);
        float s = 0.f;
        #pragma unroll 7
        for (int i = st; i < 784; i += 128) {
            float4 v = __ldg(xp + i);
            s += (v.x + v.y) + (v.z + v.w);
        }
        #pragma unroll
        for (int o = 16; o; o >>= 1) s += __shfl_xor_sync(0xffffffffu, s, o);
        if (lane == 0) part[(sub << 2) + ((st >> 5) & 3)] = s;
    }
    __syncthreads();
    if (tid < 2) {
        float s = part[tid * 4] + part[tid * 4 + 1] + part[tid * 4 + 2] + part[tid * 4 + 3];
        g_pooled[b * 256 + c0 + tid] = s * (1.0f / 3136.f);
    }
    __syncthreads();

    // ---------- release + arrive, then acquire-spin for whole sample ----------
    if (tid == 0) {
        __threadfence();
        atomicAdd(&g_done[b], 1u);
        volatile unsigned* dp = &g_done[b];
        while (*dp < 128u) __nanosleep(64);
        __threadfence();
    }
    __syncthreads();

    // ---------- phase 2: load pooled vector, compute our 18 kern rows ----------
    psh[tid] = g_pooled[b * 256 + tid];
    __syncthreads();

    {
        // warp w: rows 2w, 2w+1; warps 0,1 additionally rows 16,17
        #pragma unroll
        for (int sl = 0; sl < 3; sl++) {
            int r = (sl < 2) ? (2 * warp + sl) : (16 + warp);
            if (sl == 2 && warp >= 2) break;
            const int o = c0 * 9 + r;               // global Wk row
            const float* wr = Wk + (size_t)o * 256;
            float a = 0.f;
            #pragma unroll
            for (int i = 0; i < 8; i++)
                a = fmaf(__ldg(wr + lane + 32 * i), psh[lane + 32 * i], a);
            #pragma unroll
            for (int off = 16; off; off >>= 1) a += __shfl_xor_sync(0xffffffffu, a, off);
            if (lane == 0) kern_s[r] = fmaxf(a + __ldg(bk + o), 0.f);
        }
    }
    __syncthreads();

    // ---------- phase 3: depthwise 3x3 on our two planes (x is L2-hot) ----------
    if (tid >= 224) return;             // no barriers below
    const int pl = tid / 112;
    const int u  = tid % 112;
    const int cgp = u % 14;
    const int rg  = u / 14;
    const int xc = cgp * 4;
    const int y0 = rg * 7;
    const bool lok = cgp > 0;
    const bool rok = cgp < 13;

    const float* kp = kern_s + pl * 9;
    const float k0 = kp[0], k1 = kp[1], k2 = kp[2];
    const float k3 = kp[3], k4 = kp[4], k5 = kp[5];
    const float k6 = kp[6], k7 = kp[7], k8 = kp[8];

    const size_t plane = (size_t)b * 256 + c0 + pl;
    const float* xp = x + plane * HW + xc;

    float4 ca; float la, ra;
    float4 cb; float lb, rb;

    if (rg > 0) {
        const float* p = xp + (y0 - 1) * 56;
        ca = __ldg(reinterpret_cast<const float4*>(p));
        la = lok ? __ldg(p - 1) : 0.f;
        ra = rok ? __ldg(p + 4) : 0.f;
    } else {
        ca = make_float4(0.f, 0.f, 0.f, 0.f); la = 0.f; ra = 0.f;
    }
    {
        const float* p = xp + y0 * 56;
        cb = __ldg(reinterpret_cast<const float4*>(p));
        lb = lok ? __ldg(p - 1) : 0.f;
        rb = rok ? __ldg(p + 4) : 0.f;
    }

    float* op = out + plane * HW + y0 * 56 + xc;

    #pragma unroll
    for (int r = 0; r < 7; r++) {
        const int y = y0 + r + 1;
        float4 cc; float lc, rc;
        if (y < 56) {
            const float* p = xp + y * 56;
            cc = __ldg(reinterpret_cast<const float4*>(p));
            lc = lok ? __ldg(p - 1) : 0.f;
            rc = rok ? __ldg(p + 4) : 0.f;
        } else {
            cc = make_float4(0.f, 0.f, 0.f, 0.f); lc = 0.f; rc = 0.f;
        }

        float4 acc;
        acc.x = k0 * la;
        acc.x = fmaf(k1, ca.x, acc.x); acc.x = fmaf(k2, ca.y, acc.x);
        acc.x = fmaf(k3, lb,   acc.x); acc.x = fmaf(k4, cb.x, acc.x);
        acc.x = fmaf(k5, cb.y, acc.x); acc.x = fmaf(k6, lc,   acc.x);
        acc.x = fmaf(k7, cc.x, acc.x); acc.x = fmaf(k8, cc.y, acc.x);

        acc.y = k0 * ca.x;
        acc.y = fmaf(k1, ca.y, acc.y); acc.y = fmaf(k2, ca.z, acc.y);
        acc.y = fmaf(k3, cb.x, acc.y); acc.y = fmaf(k4, cb.y, acc.y);
        acc.y = fmaf(k5, cb.z, acc.y); acc.y = fmaf(k6, cc.x, acc.y);
        acc.y = fmaf(k7, cc.y, acc.y); acc.y = fmaf(k8, cc.z, acc.y);

        acc.z = k0 * ca.y;
        acc.z = fmaf(k1, ca.z, acc.z); acc.z = fmaf(k2, ca.w, acc.z);
        acc.z = fmaf(k3, cb.y, acc.z); acc.z = fmaf(k4, cb.z, acc.z);
        acc.z = fmaf(k5, cb.w, acc.z); acc.z = fmaf(k6, cc.y, acc.z);
        acc.z = fmaf(k7, cc.z, acc.z); acc.z = fmaf(k8, cc.w, acc.z);

        acc.w = k0 * ca.z;
        acc.w = fmaf(k1, ca.w, acc.w); acc.w = fmaf(k2, ra,   acc.w);
        acc.w = fmaf(k3, cb.z, acc.w); acc.w = fmaf(k4, cb.w, acc.w);
        acc.w = fmaf(k5, rb,   acc.w); acc.w = fmaf(k6, cc.z, acc.w);
        acc.w = fmaf(k7, cc.w, acc.w); acc.w = fmaf(k8, rc,   acc.w);

        __stcs(reinterpret_cast<float4*>(op + r * 56), acc);

        ca = cb; la = lb; ra = rb;
        cb = cc; lb = lc; rb = rc;
    }
}

extern "C" void kernel_launch(void* const* d_in, const int* in_sizes, int n_in,
                              void* d_out, int out_size) {
    const float* x  = (const float*)d_in[0];   // [32,256,56,56]
    const float* Wk = (const float*)d_in[1];   // [2304,256]
    const float* bk = (const float*)d_in[2];   // [2304]
    float* out = (float*)d_out;

    reset_kernel<<<1, 32>>>();
    fused_kernel<<<4096, 256>>>(x, Wk, bk, out);
}

// round 7
// speedup vs baseline: 3.2380x; 1.1963x over previous
#include <cuda_runtime.h>

#define HW 3136

__device__ float g_pooled[32 * 256];

// ---------------- K1: global average pool (4 planes / block) ----------------
__global__ void __launch_bounds__(256) pool_kernel(const float* __restrict__ x) {
    const int plane0 = blockIdx.x * 4;
    const float4* xp = reinterpret_cast<const float4*>(x + (size_t)plane0 * HW);
    float s0 = 0.f, s1 = 0.f, s2 = 0.f, s3 = 0.f;
    for (int i = threadIdx.x; i < 784; i += 256) {
        float4 a = xp[i];
        float4 b = xp[i + 784];
        float4 c = xp[i + 1568];
        float4 d = xp[i + 2352];
        s0 += (a.x + a.y) + (a.z + a.w);
        s1 += (b.x + b.y) + (b.z + b.w);
        s2 += (c.x + c.y) + (c.z + c.w);
        s3 += (d.x + d.y) + (d.z + d.w);
    }
    #pragma unroll
    for (int o = 16; o; o >>= 1) {
        s0 += __shfl_xor_sync(0xffffffffu, s0, o);
        s1 += __shfl_xor_sync(0xffffffffu, s1, o);
        s2 += __shfl_xor_sync(0xffffffffu, s2, o);
        s3 += __shfl_xor_sync(0xffffffffu, s3, o);
    }
    __shared__ float sh[8][4];
    if ((threadIdx.x & 31) == 0) {
        const int w = threadIdx.x >> 5;
        sh[w][0] = s0; sh[w][1] = s1; sh[w][2] = s2; sh[w][3] = s3;
    }
    __syncthreads();
    if (threadIdx.x < 32) {
        const int pl = threadIdx.x & 3;
        const int w  = threadIdx.x >> 2;
        float v = (w < 8) ? sh[w][pl] : 0.f;
        v += __shfl_xor_sync(0xffffffffu, v, 16);
        v += __shfl_xor_sync(0xffffffffu, v, 8);
        v += __shfl_xor_sync(0xffffffffu, v, 4);
        if (w == 0) g_pooled[plane0 + pl] = v * (1.0f / 3136.f);
    }
}

// ---------------- K2: kgen (own 18 rows) + depthwise 3x3 on 2 planes ----------------
__global__ void __launch_bounds__(256) kconv_kernel(const float* __restrict__ x,
                                                    const float* __restrict__ Wk,
                                                    const float* __restrict__ bk,
                                                    float* __restrict__ out)
{
    __shared__ float psh[256];
    __shared__ float kern_s[18];

    const int bid  = blockIdx.x;
    const int b    = bid >> 7;
    const int pair = bid & 127;
    const int tid  = threadIdx.x;
    const int warp = tid >> 5, lane = tid & 31;
    const int c0   = pair * 2;

    psh[tid] = g_pooled[b * 256 + tid];
    __syncthreads();

    // kernel rows c0*9 .. c0*9+17: warp w -> rows 2w, 2w+1; warps 0,1 also 16,17
    #pragma unroll
    for (int sl = 0; sl < 3; sl++) {
        if (sl == 2 && warp >= 2) break;
        const int r = (sl < 2) ? (2 * warp + sl) : (16 + warp);
        const int o = c0 * 9 + r;
        const float* wr = Wk + (size_t)o * 256;
        float a = 0.f;
        #pragma unroll
        for (int i = 0; i < 8; i++)
            a = fmaf(__ldg(wr + lane + 32 * i), psh[lane + 32 * i], a);
        #pragma unroll
        for (int off = 16; off; off >>= 1) a += __shfl_xor_sync(0xffffffffu, a, off);
        if (lane == 0) kern_s[r] = fmaxf(a + __ldg(bk + o), 0.f);
    }
    __syncthreads();

    // conv: 224 threads, thread owns 4 cols x 7 rows of one plane
    if (tid >= 224) return;
    const int pl = tid / 112;
    const int u  = tid % 112;
    const int cgp = u % 14;
    const int rg  = u / 14;
    const int xc = cgp * 4;
    const int y0 = rg * 7;
    const bool lok = cgp > 0;
    const bool rok = cgp < 13;

    const float* kp = kern_s + pl * 9;
    const float k0 = kp[0], k1 = kp[1], k2 = kp[2];
    const float k3 = kp[3], k4 = kp[4], k5 = kp[5];
    const float k6 = kp[6], k7 = kp[7], k8 = kp[8];

    const size_t plane = (size_t)b * 256 + c0 + pl;
    const float* xp = x + plane * HW + xc;

    float4 ca; float la, ra;
    float4 cb; float lb, rb;

    if (rg > 0) {
        const float* p = xp + (y0 - 1) * 56;
        ca = __ldg(reinterpret_cast<const float4*>(p));
        la = lok ? __ldg(p - 1) : 0.f;
        ra = rok ? __ldg(p + 4) : 0.f;
    } else {
        ca = make_float4(0.f, 0.f, 0.f, 0.f); la = 0.f; ra = 0.f;
    }
    {
        const float* p = xp + y0 * 56;
        cb = __ldg(reinterpret_cast<const float4*>(p));
        lb = lok ? __ldg(p - 1) : 0.f;
        rb = rok ? __ldg(p + 4) : 0.f;
    }

    float* op = out + plane * HW + y0 * 56 + xc;

    #pragma unroll
    for (int r = 0; r < 7; r++) {
        const int y = y0 + r + 1;
        float4 cc; float lc, rc;
        if (y < 56) {
            const float* p = xp + y * 56;
            cc = __ldg(reinterpret_cast<const float4*>(p));
            lc = lok ? __ldg(p - 1) : 0.f;
            rc = rok ? __ldg(p + 4) : 0.f;
        } else {
            cc = make_float4(0.f, 0.f, 0.f, 0.f); lc = 0.f; rc = 0.f;
        }

        float4 acc;
        acc.x = k0 * la;
        acc.x = fmaf(k1, ca.x, acc.x); acc.x = fmaf(k2, ca.y, acc.x);
        acc.x = fmaf(k3, lb,   acc.x); acc.x = fmaf(k4, cb.x, acc.x);
        acc.x = fmaf(k5, cb.y, acc.x); acc.x = fmaf(k6, lc,   acc.x);
        acc.x = fmaf(k7, cc.x, acc.x); acc.x = fmaf(k8, cc.y, acc.x);

        acc.y = k0 * ca.x;
        acc.y = fmaf(k1, ca.y, acc.y); acc.y = fmaf(k2, ca.z, acc.y);
        acc.y = fmaf(k3, cb.x, acc.y); acc.y = fmaf(k4, cb.y, acc.y);
        acc.y = fmaf(k5, cb.z, acc.y); acc.y = fmaf(k6, cc.x, acc.y);
        acc.y = fmaf(k7, cc.y, acc.y); acc.y = fmaf(k8, cc.z, acc.y);

        acc.z = k0 * ca.y;
        acc.z = fmaf(k1, ca.z, acc.z); acc.z = fmaf(k2, ca.w, acc.z);
        acc.z = fmaf(k3, cb.y, acc.z); acc.z = fmaf(k4, cb.z, acc.z);
        acc.z = fmaf(k5, cb.w, acc.z); acc.z = fmaf(k6, cc.y, acc.z);
        acc.z = fmaf(k7, cc.z, acc.z); acc.z = fmaf(k8, cc.w, acc.z);

        acc.w = k0 * ca.z;
        acc.w = fmaf(k1, ca.w, acc.w); acc.w = fmaf(k2, ra,   acc.w);
        acc.w = fmaf(k3, cb.z, acc.w); acc.w = fmaf(k4, cb.w, acc.w);
        acc.w = fmaf(k5, rb,   acc.w); acc.w = fmaf(k6, cc.z, acc.w);
        acc.w = fmaf(k7, cc.w, acc.w); acc.w = fmaf(k8, rc,   acc.w);

        __stcs(reinterpret_cast<float4*>(op + r * 56), acc);

        ca = cb; la = lb; ra = rb;
        cb = cc; lb = lc; rb = rc;
    }
}

extern "C" void kernel_launch(void* const* d_in, const int* in_sizes, int n_in,
                              void* d_out, int out_size) {
    const float* x  = (const float*)d_in[0];   // [32,256,56,56]
    const float* Wk = (const float*)d_in[1];   // [2304,256]
    const float* bk = (const float*)d_in[2];   // [2304]
    float* out = (float*)d_out;

    pool_kernel<<<2048, 256>>>(x);
    kconv_kernel<<<4096, 256>>>(x, Wk, bk, out);
}

// round 9
// speedup vs baseline: 3.3350x; 1.0300x over previous
#include <cuda_runtime.h>

#define HW 3136

__device__ float g_pooled[32 * 256];

// ---------------- K1: global average pool (4 planes / block, 8-deep load batches) ----------------
__global__ void __launch_bounds__(256) pool_kernel(const float* __restrict__ x) {
    const int plane0 = blockIdx.x * 4;
    const float4* xp = reinterpret_cast<const float4*>(x + (size_t)plane0 * HW);
    const int tid = threadIdx.x;
    float s0 = 0.f, s1 = 0.f, s2 = 0.f, s3 = 0.f;

    {
        float4 a0 = xp[tid],        b0 = xp[tid + 784],
               c0 = xp[tid + 1568], d0 = xp[tid + 2352];
        float4 a1 = xp[tid + 256],  b1 = xp[tid + 1040],
               c1 = xp[tid + 1824], d1 = xp[tid + 2608];
        s0 = (a0.x + a0.y) + (a0.z + a0.w) + (a1.x + a1.y) + (a1.z + a1.w);
        s1 = (b0.x + b0.y) + (b0.z + b0.w) + (b1.x + b1.y) + (b1.z + b1.w);
        s2 = (c0.x + c0.y) + (c0.z + c0.w) + (c1.x + c1.y) + (c1.z + c1.w);
        s3 = (d0.x + d0.y) + (d0.z + d0.w) + (d1.x + d1.y) + (d1.z + d1.w);
    }
    {
        float4 a = xp[tid + 512], b = xp[tid + 1296],
               c = xp[tid + 2080], d = xp[tid + 2864];
        s0 += (a.x + a.y) + (a.z + a.w);
        s1 += (b.x + b.y) + (b.z + b.w);
        s2 += (c.x + c.y) + (c.z + c.w);
        s3 += (d.x + d.y) + (d.z + d.w);
    }
    if (tid < 16) {
        float4 a = xp[tid + 768], b = xp[tid + 1552],
               c = xp[tid + 2336], d = xp[tid + 3120];
        s0 += (a.x + a.y) + (a.z + a.w);
        s1 += (b.x + b.y) + (b.z + b.w);
        s2 += (c.x + c.y) + (c.z + c.w);
        s3 += (d.x + d.y) + (d.z + d.w);
    }

    #pragma unroll
    for (int o = 16; o; o >>= 1) {
        s0 += __shfl_xor_sync(0xffffffffu, s0, o);
        s1 += __shfl_xor_sync(0xffffffffu, s1, o);
        s2 += __shfl_xor_sync(0xffffffffu, s2, o);
        s3 += __shfl_xor_sync(0xffffffffu, s3, o);
    }
    __shared__ float sh[8][4];
    if ((tid & 31) == 0) {
        const int w = tid >> 5;
        sh[w][0] = s0; sh[w][1] = s1; sh[w][2] = s2; sh[w][3] = s3;
    }
    __syncthreads();
    if (tid < 32) {
        const int pl = tid & 3;
        const int w  = tid >> 2;
        float v = (w < 8) ? sh[w][pl] : 0.f;
        v += __shfl_xor_sync(0xffffffffu, v, 16);
        v += __shfl_xor_sync(0xffffffffu, v, 8);
        v += __shfl_xor_sync(0xffffffffu, v, 4);
        if (w == 0) g_pooled[plane0 + pl] = v * (1.0f / 3136.f);
    }
}

// ---------------- K2: kgen (18 rows) + depthwise 3x3 on 2 planes ----------------
// Conv layout (lane-aligned for halo shuffles): 8 warps; each half-warp (16 lanes)
// is one (plane, row-group): grp = warp*2 + (lane>>4); pl = grp&1; rg = grp>>1.
// cgp = lane&15 (14 active column groups of 4 cols; lanes 14,15 idle).
__global__ void __launch_bounds__(256) kconv_kernel(const float* __restrict__ x,
                                                    const float* __restrict__ Wk,
                                                    const float* __restrict__ bk,
                                                    float* __restrict__ out)
{
    __shared__ float psh[256];
    __shared__ float kern_s[18];

    const int bid  = blockIdx.x;
    const int b    = bid >> 7;
    const int pair = bid & 127;
    const int tid  = threadIdx.x;
    const int warp = tid >> 5, lane = tid & 31;
    const int c0   = pair * 2;

    psh[tid] = g_pooled[b * 256 + tid];
    __syncthreads();

    // 18 rows over 8 warps: warp w -> rows 2w, 2w+1; warps 0,1 also rows 16,17
    #pragma unroll
    for (int sl = 0; sl < 3; sl++) {
        if (sl == 2 && warp >= 2) break;
        const int r = (sl < 2) ? (2 * warp + sl) : (16 + warp);
        const int o = c0 * 9 + r;
        const float* wr = Wk + (size_t)o * 256;
        float a = 0.f;
        #pragma unroll
        for (int i = 0; i < 8; i++)
            a = fmaf(__ldg(wr + lane + 32 * i), psh[lane + 32 * i], a);
        #pragma unroll
        for (int off = 16; off; off >>= 1) a += __shfl_xor_sync(0xffffffffu, a, off);
        if (lane == 0) kern_s[r] = fmaxf(a + __ldg(bk + o), 0.f);
    }
    __syncthreads();

    // ---- conv ----
    const int grp = (warp << 1) | (lane >> 4);   // 0..15
    const int pl  = grp & 1;
    const int rg  = grp >> 1;                    // 0..7
    const int cgp = lane & 15;
    const bool act = cgp < 14;
    const int xc = cgp * 4;
    const int y0 = rg * 7;
    const bool lok = act && (cgp > 0);
    const bool rok = act && (cgp < 13);

    const float* kp = kern_s + pl * 9;
    const float k0 = kp[0], k1 = kp[1], k2 = kp[2];
    const float k3 = kp[3], k4 = kp[4], k5 = kp[5];
    const float k6 = kp[6], k7 = kp[7], k8 = kp[8];

    const size_t plane = (size_t)b * 256 + c0 + pl;
    const float* xp = x + plane * HW + xc;

    // batch-load all 9 rows: R[j] = global row y0-1+j (zeros outside / inactive lanes)
    float4 R[9];
    const float4 z4 = make_float4(0.f, 0.f, 0.f, 0.f);
    R[0] = (act && rg > 0) ? __ldg(reinterpret_cast<const float4*>(xp + (y0 - 1) * 56)) : z4;
    #pragma unroll
    for (int j = 1; j < 8; j++)
        R[j] = act ? __ldg(reinterpret_cast<const float4*>(xp + (y0 - 1 + j) * 56)) : z4;
    R[8] = (act && rg < 7) ? __ldg(reinterpret_cast<const float4*>(xp + (y0 + 7) * 56)) : z4;

    // halos via intra-half-warp shuffles
    float la_ = __shfl_up_sync(0xffffffffu, R[0].w, 1);
    float ra_ = __shfl_down_sync(0xffffffffu, R[0].x, 1);
    float lb_ = __shfl_up_sync(0xffffffffu, R[1].w, 1);
    float rb_ = __shfl_down_sync(0xffffffffu, R[1].x, 1);
    float la = lok ? la_ : 0.f, ra = rok ? ra_ : 0.f;
    float lb = lok ? lb_ : 0.f, rb = rok ? rb_ : 0.f;

    float* op = out + plane * HW + y0 * 56 + xc;

    #pragma unroll
    for (int r = 0; r < 7; r++) {
        const float4 ca = R[r], cb = R[r + 1], cc = R[r + 2];
        const float lc_ = __shfl_up_sync(0xffffffffu, cc.w, 1);
        const float rc_ = __shfl_down_sync(0xffffffffu, cc.x, 1);
        const float lc = lok ? lc_ : 0.f;
        const float rc = rok ? rc_ : 0.f;

        float4 acc;
        acc.x = k0 * la;
        acc.x = fmaf(k1, ca.x, acc.x); acc.x = fmaf(k2, ca.y, acc.x);
        acc.x = fmaf(k3, lb,   acc.x); acc.x = fmaf(k4, cb.x, acc.x);
        acc.x = fmaf(k5, cb.y, acc.x); acc.x = fmaf(k6, lc,   acc.x);
        acc.x = fmaf(k7, cc.x, acc.x); acc.x = fmaf(k8, cc.y, acc.x);

        acc.y = k0 * ca.x;
        acc.y = fmaf(k1, ca.y, acc.y); acc.y = fmaf(k2, ca.z, acc.y);
        acc.y = fmaf(k3, cb.x, acc.y); acc.y = fmaf(k4, cb.y, acc.y);
        acc.y = fmaf(k5, cb.z, acc.y); acc.y = fmaf(k6, cc.x, acc.y);
        acc.y = fmaf(k7, cc.y, acc.y); acc.y = fmaf(k8, cc.z, acc.y);

        acc.z = k0 * ca.y;
        acc.z = fmaf(k1, ca.z, acc.z); acc.z = fmaf(k2, ca.w, acc.z);
        acc.z = fmaf(k3, cb.y, acc.z); acc.z = fmaf(k4, cb.z, acc.z);
        acc.z = fmaf(k5, cb.w, acc.z); acc.z = fmaf(k6, cc.y, acc.z);
        acc.z = fmaf(k7, cc.z, acc.z); acc.z = fmaf(k8, cc.w, acc.z);

        acc.w = k0 * ca.z;
        acc.w = fmaf(k1, ca.w, acc.w); acc.w = fmaf(k2, ra,   acc.w);
        acc.w = fmaf(k3, cb.z, acc.w); acc.w = fmaf(k4, cb.w, acc.w);
        acc.w = fmaf(k5, rb,   acc.w); acc.w = fmaf(k6, cc.z, acc.w);
        acc.w = fmaf(k7, cc.w, acc.w); acc.w = fmaf(k8, rc,   acc.w);

        if (act) __stcs(reinterpret_cast<float4*>(op + r * 56), acc);

        la = lb; ra = rb;
        lb = lc; rb = rc;
    }
}

extern "C" void kernel_launch(void* const* d_in, const int* in_sizes, int n_in,
                              void* d_out, int out_size) {
    const float* x  = (const float*)d_in[0];   // [32,256,56,56]
    const float* Wk = (const float*)d_in[1];   // [2304,256]
    const float* bk = (const float*)d_in[2];   // [2304]
    float* out = (float*)d_out;

    pool_kernel<<<2048, 256>>>(x);
    kconv_kernel<<<4096, 256>>>(x, Wk, bk, out);
}

// round 10
// speedup vs baseline: 3.8150x; 1.1439x over previous
#include <cuda_runtime.h>

#define HW 3136

__device__ float g_pooled[32 * 256];

// ---------------- K1: global average pool (4 planes / block, 8-deep load batches) ----------------
__global__ void __launch_bounds__(256) pool_kernel(const float* __restrict__ x) {
    const int plane0 = blockIdx.x * 4;
    const float4* xp = reinterpret_cast<const float4*>(x + (size_t)plane0 * HW);
    const int tid = threadIdx.x;
    float s0 = 0.f, s1 = 0.f, s2 = 0.f, s3 = 0.f;

    {
        float4 a0 = xp[tid],        b0 = xp[tid + 784],
               c0 = xp[tid + 1568], d0 = xp[tid + 2352];
        float4 a1 = xp[tid + 256],  b1 = xp[tid + 1040],
               c1 = xp[tid + 1824], d1 = xp[tid + 2608];
        s0 = (a0.x + a0.y) + (a0.z + a0.w) + (a1.x + a1.y) + (a1.z + a1.w);
        s1 = (b0.x + b0.y) + (b0.z + b0.w) + (b1.x + b1.y) + (b1.z + b1.w);
        s2 = (c0.x + c0.y) + (c0.z + c0.w) + (c1.x + c1.y) + (c1.z + c1.w);
        s3 = (d0.x + d0.y) + (d0.z + d0.w) + (d1.x + d1.y) + (d1.z + d1.w);
    }
    {
        float4 a = xp[tid + 512], b = xp[tid + 1296],
               c = xp[tid + 2080], d = xp[tid + 2864];
        s0 += (a.x + a.y) + (a.z + a.w);
        s1 += (b.x + b.y) + (b.z + b.w);
        s2 += (c.x + c.y) + (c.z + c.w);
        s3 += (d.x + d.y) + (d.z + d.w);
    }
    if (tid < 16) {
        float4 a = xp[tid + 768], b = xp[tid + 1552],
               c = xp[tid + 2336], d = xp[tid + 3120];
        s0 += (a.x + a.y) + (a.z + a.w);
        s1 += (b.x + b.y) + (b.z + b.w);
        s2 += (c.x + c.y) + (c.z + c.w);
        s3 += (d.x + d.y) + (d.z + d.w);
    }

    #pragma unroll
    for (int o = 16; o; o >>= 1) {
        s0 += __shfl_xor_sync(0xffffffffu, s0, o);
        s1 += __shfl_xor_sync(0xffffffffu, s1, o);
        s2 += __shfl_xor_sync(0xffffffffu, s2, o);
        s3 += __shfl_xor_sync(0xffffffffu, s3, o);
    }
    __shared__ float sh[8][4];
    if ((tid & 31) == 0) {
        const int w = tid >> 5;
        sh[w][0] = s0; sh[w][1] = s1; sh[w][2] = s2; sh[w][3] = s3;
    }
    __syncthreads();
    if (tid < 32) {
        const int pl = tid & 3;
        const int w  = tid >> 2;
        float v = (w < 8) ? sh[w][pl] : 0.f;
        v += __shfl_xor_sync(0xffffffffu, v, 16);
        v += __shfl_xor_sync(0xffffffffu, v, 8);
        v += __shfl_xor_sync(0xffffffffu, v, 4);
        if (w == 0) g_pooled[plane0 + pl] = v * (1.0f / 3136.f);
    }
}

// ---------------- K2: kgen (18 rows) + depthwise 3x3 on 2 planes ----------------
// Plane order REVERSED vs pool (L2 recency). Conv row loads hoisted above kgen
// so kgen math hides their latency. Half-warp = (plane,row-group); cgp = lane&15.
__global__ void __launch_bounds__(256) kconv_kernel(const float* __restrict__ x,
                                                    const float* __restrict__ Wk,
                                                    const float* __restrict__ bk,
                                                    float* __restrict__ out)
{
    __shared__ float psh[256];
    __shared__ float kern_s[18];

    const int gid  = 4095 - blockIdx.x;      // reverse: first wave gets L2-hottest planes
    const int b    = gid >> 7;
    const int pair = gid & 127;
    const int tid  = threadIdx.x;
    const int warp = tid >> 5, lane = tid & 31;
    const int c0   = pair * 2;

    // ---- conv geometry ----
    const int grp = (warp << 1) | (lane >> 4);   // 0..15
    const int pl  = grp & 1;
    const int rg  = grp >> 1;                    // 0..7
    const int cgp = lane & 15;
    const bool act = cgp < 14;
    const int xc = cgp * 4;
    const int y0 = rg * 7;
    const bool lok = act && (cgp > 0);
    const bool rok = act && (cgp < 13);

    const size_t plane = (size_t)b * 256 + c0 + pl;
    const float* xp = x + plane * HW + xc;

    // ---- hoisted conv loads: 9 rows in flight while kgen computes ----
    float4 R[9];
    const float4 z4 = make_float4(0.f, 0.f, 0.f, 0.f);
    R[0] = (act && rg > 0) ? __ldg(reinterpret_cast<const float4*>(xp + (y0 - 1) * 56)) : z4;
    #pragma unroll
    for (int j = 1; j < 8; j++)
        R[j] = act ? __ldg(reinterpret_cast<const float4*>(xp + (y0 - 1 + j) * 56)) : z4;
    R[8] = (act && rg < 7) ? __ldg(reinterpret_cast<const float4*>(xp + (y0 + 7) * 56)) : z4;

    // ---- kgen: 18 rows over 8 warps ----
    psh[tid] = g_pooled[b * 256 + tid];
    __syncthreads();

    #pragma unroll
    for (int sl = 0; sl < 3; sl++) {
        if (sl == 2 && warp >= 2) break;
        const int r = (sl < 2) ? (2 * warp + sl) : (16 + warp);
        const int o = c0 * 9 + r;
        const float* wr = Wk + (size_t)o * 256;
        float a = 0.f;
        #pragma unroll
        for (int i = 0; i < 8; i++)
            a = fmaf(__ldg(wr + lane + 32 * i), psh[lane + 32 * i], a);
        #pragma unroll
        for (int off = 16; off; off >>= 1) a += __shfl_xor_sync(0xffffffffu, a, off);
        if (lane == 0) kern_s[r] = fmaxf(a + __ldg(bk + o), 0.f);
    }
    __syncthreads();

    const float* kp = kern_s + pl * 9;
    const float k0 = kp[0], k1 = kp[1], k2 = kp[2];
    const float k3 = kp[3], k4 = kp[4], k5 = kp[5];
    const float k6 = kp[6], k7 = kp[7], k8 = kp[8];

    // halos via intra-half-warp shuffles
    float la_ = __shfl_up_sync(0xffffffffu, R[0].w, 1);
    float ra_ = __shfl_down_sync(0xffffffffu, R[0].x, 1);
    float lb_ = __shfl_up_sync(0xffffffffu, R[1].w, 1);
    float rb_ = __shfl_down_sync(0xffffffffu, R[1].x, 1);
    float la = lok ? la_ : 0.f, ra = rok ? ra_ : 0.f;
    float lb = lok ? lb_ : 0.f, rb = rok ? rb_ : 0.f;

    float* op = out + plane * HW + y0 * 56 + xc;

    #pragma unroll
    for (int r = 0; r < 7; r++) {
        const float4 ca = R[r], cb = R[r + 1], cc = R[r + 2];
        const float lc_ = __shfl_up_sync(0xffffffffu, cc.w, 1);
        const float rc_ = __shfl_down_sync(0xffffffffu, cc.x, 1);
        const float lc = lok ? lc_ : 0.f;
        const float rc = rok ? rc_ : 0.f;

        float4 acc;
        acc.x = k0 * la;
        acc.x = fmaf(k1, ca.x, acc.x); acc.x = fmaf(k2, ca.y, acc.x);
        acc.x = fmaf(k3, lb,   acc.x); acc.x = fmaf(k4, cb.x, acc.x);
        acc.x = fmaf(k5, cb.y, acc.x); acc.x = fmaf(k6, lc,   acc.x);
        acc.x = fmaf(k7, cc.x, acc.x); acc.x = fmaf(k8, cc.y, acc.x);

        acc.y = k0 * ca.x;
        acc.y = fmaf(k1, ca.y, acc.y); acc.y = fmaf(k2, ca.z, acc.y);
        acc.y = fmaf(k3, cb.x, acc.y); acc.y = fmaf(k4, cb.y, acc.y);
        acc.y = fmaf(k5, cb.z, acc.y); acc.y = fmaf(k6, cc.x, acc.y);
        acc.y = fmaf(k7, cc.y, acc.y); acc.y = fmaf(k8, cc.z, acc.y);

        acc.z = k0 * ca.y;
        acc.z = fmaf(k1, ca.z, acc.z); acc.z = fmaf(k2, ca.w, acc.z);
        acc.z = fmaf(k3, cb.y, acc.z); acc.z = fmaf(k4, cb.z, acc.z);
        acc.z = fmaf(k5, cb.w, acc.z); acc.z = fmaf(k6, cc.y, acc.z);
        acc.z = fmaf(k7, cc.z, acc.z); acc.z = fmaf(k8, cc.w, acc.z);

        acc.w = k0 * ca.z;
        acc.w = fmaf(k1, ca.w, acc.w); acc.w = fmaf(k2, ra,   acc.w);
        acc.w = fmaf(k3, cb.z, acc.w); acc.w = fmaf(k4, cb.w, acc.w);
        acc.w = fmaf(k5, rb,   acc.w); acc.w = fmaf(k6, cc.z, acc.w);
        acc.w = fmaf(k7, cc.w, acc.w); acc.w = fmaf(k8, rc,   acc.w);

        if (act) __stcs(reinterpret_cast<float4*>(op + r * 56), acc);

        la = lb; ra = rb;
        lb = lc; rb = rc;
    }
}

extern "C" void kernel_launch(void* const* d_in, const int* in_sizes, int n_in,
                              void* d_out, int out_size) {
    const float* x  = (const float*)d_in[0];   // [32,256,56,56]
    const float* Wk = (const float*)d_in[1];   // [2304,256]
    const float* bk = (const float*)d_in[2];   // [2304]
    float* out = (float*)d_out;

    pool_kernel<<<2048, 256>>>(x);
    kconv_kernel<<<4096, 256>>>(x, Wk, bk, out);
}